// round 7
// baseline (speedup 1.0000x reference)
#include <cuda_runtime.h>

// ============================================================================
// QuantumLayer (4 qubits, 2 layers, BATCH=524288), Heisenberg picture,
// TWO INDEPENDENT SCALAR SAMPLES PER THREAD (ILP + coef-load amortization).
//
// Per wire q: |psi_q> = RZ(phi_q) RY(a_q)|0>, a_q = pi*tanh(x_q)+w[0][q][0],
// phi_q = w[0][q][1]. Bloch: X=sin a cos phi, Y=sin a sin phi, Z=cos a.
// Conjugating Z_q through ring2 / RY-layer (Z->cos t Z - sin t X) / ring1
// gives 36 Pauli-string terms; coefficients are weight-only (shared memory),
// per-sample factors are products of Bloch components.
// ============================================================================

__constant__ unsigned short c_tbl[36] = {
    // q0: ZZZ,ZZX,ZXZ,ZXX,XZZ,XZX,XXZ,XXX over wires {1,2,3} (+extras)
    0x0E0, 0x1E8, 0x0E4, 0x1EC, 0x1E2, 0x1EA, 0x1E6, 0x1EE,
    // q1
    0x030, 0x032, 0x031, 0x033,
    // q2
    0x070, 0x074, 0x172, 0x176, 0x171, 0x175, 0x173, 0x177,
    // q3
    0x0F0, 0x0F8, 0x1F4, 0x1FC, 0x0F2, 0x1FA, 0x0F6, 0x1FE,
    0x0F1, 0x0F9, 0x1F5, 0x1FD, 0x0F3, 0x0FB, 0x0F7, 0x0FF
};

__global__ __launch_bounds__(256)
void circuit_kernel(const float* __restrict__ x, const float* __restrict__ w,
                    float* __restrict__ out, int NPAIR) {
    __shared__ float s_cph[4], s_sph[4], s_pipw[4];
    __shared__ float s_cth[4], s_sth[4];
    __shared__ float s_coef[36];

    const int t = threadIdx.x;
    if (t < 4) {
        float sp, cp; __sincosf(w[2 * t + 1], &sp, &cp);
        s_sph[t] = sp; s_cph[t] = cp;
        s_pipw[t] = 3.14159265358979f + w[2 * t];
    } else if (t < 8) {
        int j = t - 4;
        float st, ct; __sincosf(w[8 + 2 * j], &st, &ct);
        s_sth[j] = st; s_cth[j] = ct;
    }
    __syncthreads();
    if (t < 36) {
        unsigned e = c_tbl[t];
        float v = 1.0f;
        #pragma unroll
        for (int j = 0; j < 4; j++)
            if ((e >> (4 + j)) & 1) v *= ((e >> j) & 1) ? s_sth[j] : s_cth[j];
        s_coef[t] = (e & 0x100) ? -v : v;
    }
    __syncthreads();

    int tid = blockIdx.x * blockDim.x + t;
    if (tid >= NPAIR) return;

    const float4* x4 = reinterpret_cast<const float4*>(x);
    float4 xva = x4[2 * tid];
    float4 xvb = x4[2 * tid + 1];
    float xs[2][4] = {{xva.x, xva.y, xva.z, xva.w},
                      {xvb.x, xvb.y, xvb.z, xvb.w}};

    // Per-wire Bloch vectors for both samples (independent chains -> ILP).
    float X[2][4], Y[2][4], Z[2][4];
    #pragma unroll
    for (int q = 0; q < 4; q++) {
        float cph = s_cph[q], sph = s_sph[q], pipw = s_pipw[q];
        #pragma unroll
        for (int u = 0; u < 2; u++) {
            float e  = __expf(2.0f * xs[u][q]);
            float a  = pipw - __fdividef(6.283185307179586f, e + 1.0f);
            float sa, ca; __sincosf(a, &sa, &ca);
            X[u][q] = sa * cph;
            Y[u][q] = sa * sph;
            Z[u][q] = ca;
        }
    }

    float o[2][4];

    #pragma unroll
    for (int u = 0; u < 2; u++) {
        float x01 = X[u][0]*X[u][1], y01 = Y[u][0]*Y[u][1];
        float y12 = Y[u][1]*Y[u][2], y23 = Y[u][2]*Y[u][3];
        float x12 = X[u][1]*X[u][2], x23 = X[u][2]*X[u][3];
        float z13 = Z[u][1]*Z[u][3], zx23 = Z[u][2]*X[u][3];
        float z12 = Z[u][1]*Z[u][2], x02 = X[u][0]*X[u][2];
        float z23 = Z[u][2]*Z[u][3], yz01 = Y[u][0]*Z[u][1];
        const float* C = s_coef;
        float a0, a1, a2, a3;

        // <Z_0>
        a0  = C[0] * (Z[u][0] * z13);
        a0 = fmaf(C[1], x01 * zx23, a0);
        a0 = fmaf(C[2], y23, a0);
        a0 = fmaf(C[3], y01 * X[u][2], a0);
        a0 = fmaf(C[4], x12 * Z[u][3], a0);
        a0 = fmaf(C[5], (yz01 * Y[u][2]) * X[u][3], a0);
        a0 = fmaf(C[6], ((Z[u][0] * Y[u][1]) * Z[u][2]) * Y[u][3], a0);
        a0 = fmaf(C[7], X[u][0], a0);

        // <Z_1>
        a1  = C[8] * (Z[u][0] * z23);
        a1 = fmaf(C[9],  y12 * Z[u][3], a1);
        a1 = fmaf(C[10], y01, a1);
        a1 = fmaf(C[11], x02, a1);

        // <Z_2>
        a2  = C[12] * z13;
        a2 = fmaf(C[13], Z[u][0] * y23, a2);
        a2 = fmaf(C[14], (Z[u][0] * x12) * Z[u][3], a2);
        a2 = fmaf(C[15], (Y[u][1] * Z[u][2]) * Y[u][3], a2);
        a2 = fmaf(C[16], x01 * Z[u][2], a2);
        a2 = fmaf(C[17], y01 * x23, a2);
        a2 = fmaf(C[18], yz01 * Y[u][2], a2);
        a2 = fmaf(C[19], X[u][0] * X[u][3], a2);

        // <Z_3>
        a3  = C[20] * (Z[u][0] * Z[u][2]);
        a3 = fmaf(C[21], X[u][0] * (Y[u][1] * Y[u][3]), a3);
        a3 = fmaf(C[22], Z[u][1] * x23, a3);
        a3 = fmaf(C[23], ((Y[u][0] * X[u][1]) * Y[u][2]) * Z[u][3], a3);
        a3 = fmaf(C[24], y12, a3);
        a3 = fmaf(C[25], (Y[u][0] * X[u][2]) * Y[u][3], a3);
        a3 = fmaf(C[26], Z[u][0] * (X[u][1] * X[u][3]), a3);
        a3 = fmaf(C[27], (X[u][0] * z12) * Z[u][3], a3);
        a3 = fmaf(C[28], y01 * Z[u][3], a3);
        a3 = fmaf(C[29], zx23, a3);
        a3 = fmaf(C[30], x01 * y23, a3);
        a3 = fmaf(C[31], (Z[u][0] * Z[u][1]) * X[u][2], a3);
        a3 = fmaf(C[32], x02 * Z[u][3], a3);
        a3 = fmaf(C[33], (Z[u][0] * y12) * X[u][3], a3);
        a3 = fmaf(C[34], (yz01 * Z[u][2]) * Y[u][3], a3);
        a3 = fmaf(C[35], X[u][1], a3);

        o[u][0] = a0; o[u][1] = a1; o[u][2] = a2; o[u][3] = a3;
    }

    float4* o4 = reinterpret_cast<float4*>(out);
    float4 oa; oa.x = o[0][0]; oa.y = o[0][1]; oa.z = o[0][2]; oa.w = o[0][3];
    float4 ob; ob.x = o[1][0]; ob.y = o[1][1]; ob.z = o[1][2]; ob.w = o[1][3];
    o4[2 * tid]     = oa;
    o4[2 * tid + 1] = ob;
}

extern "C" void kernel_launch(void* const* d_in, const int* in_sizes, int n_in,
                              void* d_out, int out_size) {
    const float* x = (const float*)d_in[0];     // [B, 4]
    const float* w = (const float*)d_in[1];     // [2, 4, 2]
    float* out = (float*)d_out;                 // [B, 4]
    int B = in_sizes[0] / 4;
    int npair = B / 2;                           // B even

    int threads = 256;
    int blocks = (npair + threads - 1) / threads;
    circuit_kernel<<<blocks, threads>>>(x, w, out, npair);
}

// round 8
// speedup vs baseline: 1.0208x; 1.0208x over previous
#include <cuda_runtime.h>

// ============================================================================
// QuantumLayer (4q, 2 layers, B=524288), Heisenberg picture.
// 2 samples/thread; encoding scalar (MUFU), 36-term Pauli tree fully packed
// in f32x2 (SASS FFMA2/FMUL2) across the two samples -> issue-slot compression
// in an issue-bound kernel with idle pipes.
// ============================================================================

using u64 = unsigned long long;

__device__ __forceinline__ u64 mul2(u64 a, u64 b) {
    u64 d; asm("mul.rn.f32x2 %0, %1, %2;" : "=l"(d) : "l"(a), "l"(b)); return d;
}
__device__ __forceinline__ u64 fma2(u64 a, u64 b, u64 c) {
    u64 d; asm("fma.rn.f32x2 %0, %1, %2, %3;" : "=l"(d) : "l"(a), "l"(b), "l"(c)); return d;
}
__device__ __forceinline__ u64 pk(float lo, float hi) {
    u64 d; asm("mov.b64 %0, {%1, %2};" : "=l"(d) : "f"(lo), "f"(hi)); return d;
}
__device__ __forceinline__ float2 upk(u64 a) {
    float2 r; asm("mov.b64 {%0, %1}, %2;" : "=f"(r.x), "=f"(r.y) : "l"(a)); return r;
}

// Term table: bits0-3 = sin-selection S, bits4-7 = wire-set W, bit8 = sign.
__constant__ unsigned short c_tbl[36] = {
    0x0E0, 0x1E8, 0x0E4, 0x1EC, 0x1E2, 0x1EA, 0x1E6, 0x1EE,   // q0
    0x030, 0x032, 0x031, 0x033,                                 // q1
    0x070, 0x074, 0x172, 0x176, 0x171, 0x175, 0x173, 0x177,     // q2
    0x0F0, 0x0F8, 0x1F4, 0x1FC, 0x0F2, 0x1FA, 0x0F6, 0x1FE,     // q3
    0x0F1, 0x0F9, 0x1F5, 0x1FD, 0x0F3, 0x0FB, 0x0F7, 0x0FF
};

__global__ __launch_bounds__(256)
void circuit_kernel(const float* __restrict__ x, const float* __restrict__ w,
                    float* __restrict__ out, int NPAIR) {
    __shared__ u64   s_cph2[4], s_sph2[4];        // packed cos/sin(phi_q)
    __shared__ float s_pipw[4];                   // pi + w0y_q
    __shared__ float s_cth[4], s_sth[4];          // layer-1 theta trig
    __shared__ u64   s_coef[36];                  // packed (dup-lane) coefs

    const int t = threadIdx.x;
    if (t < 4) {
        float sp, cp; __sincosf(w[2 * t + 1], &sp, &cp);
        s_sph2[t] = pk(sp, sp); s_cph2[t] = pk(cp, cp);
        s_pipw[t] = 3.14159265358979f + w[2 * t];
    } else if (t < 8) {
        int j = t - 4;
        float st, ct; __sincosf(w[8 + 2 * j], &st, &ct);
        s_sth[j] = st; s_cth[j] = ct;
    }
    __syncthreads();
    if (t < 36) {
        unsigned e = c_tbl[t];
        float v = 1.0f;
        #pragma unroll
        for (int j = 0; j < 4; j++)
            if ((e >> (4 + j)) & 1) v *= ((e >> j) & 1) ? s_sth[j] : s_cth[j];
        if (e & 0x100) v = -v;
        s_coef[t] = pk(v, v);
    }
    __syncthreads();

    int tid = blockIdx.x * blockDim.x + t;
    if (tid >= NPAIR) return;

    const float4* x4 = reinterpret_cast<const float4*>(x);
    float4 xva = x4[2 * tid];
    float4 xvb = x4[2 * tid + 1];
    float xa[4] = {xva.x, xva.y, xva.z, xva.w};
    float xb[4] = {xvb.x, xvb.y, xvb.z, xvb.w};

    // Bloch vectors, packed across the two samples.
    u64 X[4], Y[4], Z[4];
    #pragma unroll
    for (int q = 0; q < 4; q++) {
        float pipw = s_pipw[q];
        float eA = __expf(2.0f * xa[q]);
        float aA = pipw - __fdividef(6.283185307179586f, eA + 1.0f);
        float sA, cA; __sincosf(aA, &sA, &cA);
        float eB = __expf(2.0f * xb[q]);
        float aB = pipw - __fdividef(6.283185307179586f, eB + 1.0f);
        float sB, cB; __sincosf(aB, &sB, &cB);
        u64 sa = pk(sA, sB);
        Z[q] = pk(cA, cB);
        X[q] = mul2(sa, s_cph2[q]);
        Y[q] = mul2(sa, s_sph2[q]);
    }

    // Shared sub-products (packed).
    u64 x01 = mul2(X[0], X[1]), y01 = mul2(Y[0], Y[1]);
    u64 y12 = mul2(Y[1], Y[2]), y23 = mul2(Y[2], Y[3]);
    u64 x12 = mul2(X[1], X[2]), x23 = mul2(X[2], X[3]);
    u64 z13 = mul2(Z[1], Z[3]), zx23 = mul2(Z[2], X[3]);
    u64 z12 = mul2(Z[1], Z[2]), x02 = mul2(X[0], X[2]);
    u64 z23 = mul2(Z[2], Z[3]), yz01 = mul2(Y[0], Z[1]);

    const u64* C = s_coef;
    u64 a0, a1, a2, a3;

    // <Z_0>
    a0 = mul2(C[0], mul2(Z[0], z13));
    a0 = fma2(C[1], mul2(x01, zx23), a0);
    a0 = fma2(C[2], y23, a0);
    a0 = fma2(C[3], mul2(y01, X[2]), a0);
    a0 = fma2(C[4], mul2(x12, Z[3]), a0);
    a0 = fma2(C[5], mul2(mul2(yz01, Y[2]), X[3]), a0);
    a0 = fma2(C[6], mul2(mul2(mul2(Z[0], Y[1]), Z[2]), Y[3]), a0);
    a0 = fma2(C[7], X[0], a0);

    // <Z_1>
    a1 = mul2(C[8], mul2(Z[0], z23));
    a1 = fma2(C[9],  mul2(y12, Z[3]), a1);
    a1 = fma2(C[10], y01, a1);
    a1 = fma2(C[11], x02, a1);

    // <Z_2>
    a2 = mul2(C[12], z13);
    a2 = fma2(C[13], mul2(Z[0], y23), a2);
    a2 = fma2(C[14], mul2(mul2(Z[0], x12), Z[3]), a2);
    a2 = fma2(C[15], mul2(mul2(Y[1], Z[2]), Y[3]), a2);
    a2 = fma2(C[16], mul2(x01, Z[2]), a2);
    a2 = fma2(C[17], mul2(y01, x23), a2);
    a2 = fma2(C[18], mul2(yz01, Y[2]), a2);
    a2 = fma2(C[19], mul2(X[0], X[3]), a2);

    // <Z_3>
    a3 = mul2(C[20], mul2(Z[0], Z[2]));
    a3 = fma2(C[21], mul2(X[0], mul2(Y[1], Y[3])), a3);
    a3 = fma2(C[22], mul2(Z[1], x23), a3);
    a3 = fma2(C[23], mul2(mul2(mul2(Y[0], X[1]), Y[2]), Z[3]), a3);
    a3 = fma2(C[24], y12, a3);
    a3 = fma2(C[25], mul2(mul2(Y[0], X[2]), Y[3]), a3);
    a3 = fma2(C[26], mul2(Z[0], mul2(X[1], X[3])), a3);
    a3 = fma2(C[27], mul2(mul2(X[0], z12), Z[3]), a3);
    a3 = fma2(C[28], mul2(y01, Z[3]), a3);
    a3 = fma2(C[29], zx23, a3);
    a3 = fma2(C[30], mul2(x01, y23), a3);
    a3 = fma2(C[31], mul2(mul2(Z[0], Z[1]), X[2]), a3);
    a3 = fma2(C[32], mul2(x02, Z[3]), a3);
    a3 = fma2(C[33], mul2(mul2(Z[0], y12), X[3]), a3);
    a3 = fma2(C[34], mul2(mul2(yz01, Z[2]), Y[3]), a3);
    a3 = fma2(C[35], X[1], a3);

    float2 f0 = upk(a0), f1 = upk(a1), f2 = upk(a2), f3 = upk(a3);
    float4* o4 = reinterpret_cast<float4*>(out);
    float4 oa; oa.x = f0.x; oa.y = f1.x; oa.z = f2.x; oa.w = f3.x;
    float4 ob; ob.x = f0.y; ob.y = f1.y; ob.z = f2.y; ob.w = f3.y;
    o4[2 * tid]     = oa;
    o4[2 * tid + 1] = ob;
}

extern "C" void kernel_launch(void* const* d_in, const int* in_sizes, int n_in,
                              void* d_out, int out_size) {
    const float* x = (const float*)d_in[0];     // [B, 4]
    const float* w = (const float*)d_in[1];     // [2, 4, 2]
    float* out = (float*)d_out;                 // [B, 4]
    int B = in_sizes[0] / 4;
    int npair = B / 2;

    int threads = 256;
    int blocks = (npair + threads - 1) / threads;
    circuit_kernel<<<blocks, threads>>>(x, w, out, npair);
}

// round 9
// speedup vs baseline: 1.2294x; 1.2043x over previous
#include <cuda_runtime.h>

// ============================================================================
// QuantumLayer (4q, 2 layers, B=524288), Heisenberg picture.
// 2 samples/thread; 36-term Pauli sum packed in f32x2 across samples,
// FACTORED by the wire-3 operator (4 short independent chains per output).
// Encoding uses tanh.approx.f32 (1 MUFU) instead of exp/rcp chain.
// ============================================================================

using u64 = unsigned long long;

__device__ __forceinline__ u64 mul2(u64 a, u64 b) {
    u64 d; asm("mul.rn.f32x2 %0, %1, %2;" : "=l"(d) : "l"(a), "l"(b)); return d;
}
__device__ __forceinline__ u64 fma2(u64 a, u64 b, u64 c) {
    u64 d; asm("fma.rn.f32x2 %0, %1, %2, %3;" : "=l"(d) : "l"(a), "l"(b), "l"(c)); return d;
}
__device__ __forceinline__ u64 pk(float lo, float hi) {
    u64 d; asm("mov.b64 %0, {%1, %2};" : "=l"(d) : "f"(lo), "f"(hi)); return d;
}
__device__ __forceinline__ float2 upk(u64 a) {
    float2 r; asm("mov.b64 {%0, %1}, %2;" : "=f"(r.x), "=f"(r.y) : "l"(a)); return r;
}
__device__ __forceinline__ float tanha(float x) {
    float y; asm("tanh.approx.f32 %0, %1;" : "=f"(y) : "f"(x)); return y;
}

// Term table: bits0-3 = sin-selection S, bits4-7 = wire-set W, bit8 = sign.
__constant__ unsigned short c_tbl[36] = {
    0x0E0, 0x1E8, 0x0E4, 0x1EC, 0x1E2, 0x1EA, 0x1E6, 0x1EE,   // q0
    0x030, 0x032, 0x031, 0x033,                                 // q1
    0x070, 0x074, 0x172, 0x176, 0x171, 0x175, 0x173, 0x177,     // q2
    0x0F0, 0x0F8, 0x1F4, 0x1FC, 0x0F2, 0x1FA, 0x0F6, 0x1FE,     // q3
    0x0F1, 0x0F9, 0x1F5, 0x1FD, 0x0F3, 0x0FB, 0x0F7, 0x0FF
};

__global__ __launch_bounds__(256, 4)
void circuit_kernel(const float* __restrict__ x, const float* __restrict__ w,
                    float* __restrict__ out, int NPAIR) {
    __shared__ u64   s_cph2[4], s_sph2[4];        // packed cos/sin(phi_q)
    __shared__ float s_w0y[4];                    // layer-0 RY full angle
    __shared__ float s_cth[4], s_sth[4];
    __shared__ u64   s_coef[36];

    const int t = threadIdx.x;
    if (t < 4) {
        float sp, cp; __sincosf(w[2 * t + 1], &sp, &cp);
        s_sph2[t] = pk(sp, sp); s_cph2[t] = pk(cp, cp);
        s_w0y[t] = w[2 * t];
    } else if (t < 8) {
        int j = t - 4;
        float st, ct; __sincosf(w[8 + 2 * j], &st, &ct);
        s_sth[j] = st; s_cth[j] = ct;
    }
    __syncthreads();
    if (t < 36) {
        unsigned e = c_tbl[t];
        float v = 1.0f;
        #pragma unroll
        for (int j = 0; j < 4; j++)
            if ((e >> (4 + j)) & 1) v *= ((e >> j) & 1) ? s_sth[j] : s_cth[j];
        if (e & 0x100) v = -v;
        s_coef[t] = pk(v, v);
    }
    __syncthreads();

    int tid = blockIdx.x * blockDim.x + t;
    if (tid >= NPAIR) return;

    const float4* x4 = reinterpret_cast<const float4*>(x);
    float4 xva = x4[2 * tid];
    float4 xvb = x4[2 * tid + 1];
    float xa[4] = {xva.x, xva.y, xva.z, xva.w};
    float xb[4] = {xvb.x, xvb.y, xvb.z, xvb.w};

    // Bloch vectors (packed across the two samples).
    // Full rotation angle: a = pi*tanh(x) + w0y.
    u64 X[4], Y[4], Z[4];
    const float PI = 3.14159265358979f;
    #pragma unroll
    for (int q = 0; q < 4; q++) {
        float w0 = s_w0y[q];
        float aA = fmaf(tanha(xa[q]), PI, w0);
        float aB = fmaf(tanha(xb[q]), PI, w0);
        float sA, cA; __sincosf(aA, &sA, &cA);
        float sB, cB; __sincosf(aB, &sB, &cB);
        u64 sa = pk(sA, sB);
        Z[q] = pk(cA, cB);
        X[q] = mul2(sa, s_cph2[q]);
        Y[q] = mul2(sa, s_sph2[q]);
    }

    // Shared sub-products.
    u64 y01 = mul2(Y[0], Y[1]), x01 = mul2(X[0], X[1]);
    u64 x12 = mul2(X[1], X[2]), y12 = mul2(Y[1], Y[2]);
    u64 z01 = mul2(Z[0], Z[1]), z12 = mul2(Z[1], Z[2]);
    u64 x02 = mul2(X[0], X[2]), z02 = mul2(Z[0], Z[2]);
    u64 yz01 = mul2(Y[0], Z[1]);
    u64 x01z2 = mul2(x01, Z[2]);
    u64 yzy   = mul2(yz01, Y[2]);      // y0 z1 y2
    u64 yx2   = mul2(y01, X[2]);       // y0 y1 x2

    const u64* C = s_coef;

    // ---- <Z_0> : factor by wire-3 operator ----
    u64 g0z = fma2(C[4], x12, mul2(C[0], z01));
    u64 g0y = fma2(C[6], mul2(Y[1], z02), mul2(C[2], Y[2]));
    u64 g0x = fma2(C[5], yzy, mul2(C[1], x01z2));
    u64 g0c = fma2(C[3], yx2, mul2(C[7], X[0]));
    u64 a0 = fma2(g0z, Z[3], fma2(g0y, Y[3], fma2(g0x, X[3], g0c)));

    // ---- <Z_1> ----
    u64 g1z = fma2(C[9], y12, mul2(C[8], z02));
    u64 g1c = fma2(C[11], x02, mul2(C[10], y01));
    u64 a1 = fma2(g1z, Z[3], g1c);

    // ---- <Z_2> ----
    u64 g2z = fma2(C[14], mul2(Z[0], x12), mul2(C[12], Z[1]));
    u64 g2y = fma2(C[15], mul2(Y[1], Z[2]), mul2(C[13], mul2(Z[0], Y[2])));
    u64 g2x = fma2(C[17], yx2, mul2(C[19], X[0]));
    u64 g2c = fma2(C[16], x01z2, mul2(C[18], yzy));
    u64 a2 = fma2(g2z, Z[3], fma2(g2y, Y[3], fma2(g2x, X[3], g2c)));

    // ---- <Z_3> ----
    u64 g3z = fma2(C[23], mul2(mul2(Y[0], X[1]), Y[2]),
              fma2(C[27], mul2(X[0], z12),
              fma2(C[28], y01, mul2(C[32], x02))));
    u64 g3y = fma2(C[21], mul2(X[0], Y[1]),
              fma2(C[25], mul2(Y[0], X[2]),
              fma2(C[30], mul2(x01, Y[2]), mul2(C[34], mul2(yz01, Z[2])))));
    u64 g3x = fma2(C[22], mul2(Z[1], X[2]),
              fma2(C[26], mul2(Z[0], X[1]),
              fma2(C[33], mul2(Z[0], y12), mul2(C[29], Z[2]))));
    u64 g3c = fma2(C[20], z02,
              fma2(C[24], y12,
              fma2(C[31], mul2(z01, X[2]), mul2(C[35], X[1]))));
    u64 a3 = fma2(g3z, Z[3], fma2(g3y, Y[3], fma2(g3x, X[3], g3c)));

    float2 f0 = upk(a0), f1 = upk(a1), f2 = upk(a2), f3 = upk(a3);
    float4* o4 = reinterpret_cast<float4*>(out);
    float4 oa; oa.x = f0.x; oa.y = f1.x; oa.z = f2.x; oa.w = f3.x;
    float4 ob; ob.x = f0.y; ob.y = f1.y; ob.z = f2.y; ob.w = f3.y;
    o4[2 * tid]     = oa;
    o4[2 * tid + 1] = ob;
}

extern "C" void kernel_launch(void* const* d_in, const int* in_sizes, int n_in,
                              void* d_out, int out_size) {
    const float* x = (const float*)d_in[0];     // [B, 4]
    const float* w = (const float*)d_in[1];     // [2, 4, 2]
    float* out = (float*)d_out;                 // [B, 4]
    int B = in_sizes[0] / 4;
    int npair = B / 2;

    int threads = 256;
    int blocks = (npair + threads - 1) / threads;
    circuit_kernel<<<blocks, threads>>>(x, w, out, npair);
}